// round 8
// baseline (speedup 1.0000x reference)
#include <cuda_runtime.h>
#include <stdint.h>
#include <math.h>

#define BATCH 8
#define TLEN  512
#define CINT  512
#define CCONT 192
#define CSPK  256
#define DMLP  1536
#define NWIN  1024
#define FRAME 960
#define LTOT  (TLEN*FRAME)
#define KOUT  3584

// ---------------- scratch (device globals; c-major activations [B][C][T]) ----------------
__device__ float d_x[BATCH*CINT*TLEN];
__device__ float d_h[BATCH*CINT*TLEN];
__device__ float d_g[BATCH*DMLP*TLEN];
__device__ float d_mu[BATCH*TLEN];
__device__ float d_rs[BATCH*TLEN];
__device__ float d_spkadd[BATCH*CINT];
__device__ float d_filt[BATCH*TLEN*NWIN];

// ---------------- helpers ----------------
__device__ __forceinline__ uint32_t pkh2(float lo, float hi) {
    uint32_t r;  // d.hi = first src, d.lo = second src
    asm("cvt.rn.f16x2.f32 %0, %1, %2;" : "=r"(r) : "f"(hi), "f"(lo));
    return r;
}
__device__ __forceinline__ void mma_f16(float c[4], const uint32_t a[4], const uint32_t b[2]) {
    asm volatile("mma.sync.aligned.m16n8k16.row.col.f32.f16.f16.f32 "
                 "{%0,%1,%2,%3},{%4,%5,%6,%7},{%8,%9},{%0,%1,%2,%3};"
                 : "+f"(c[0]), "+f"(c[1]), "+f"(c[2]), "+f"(c[3])
                 : "r"(a[0]), "r"(a[1]), "r"(a[2]), "r"(a[3]), "r"(b[0]), "r"(b[1]));
}
__device__ __forceinline__ float gelu_exact(float v) {
    return 0.5f*v*(1.f + erff(v*0.70710678118654752f));
}
__device__ __forceinline__ void fma2(unsigned long long& acc, unsigned long long a,
                                     unsigned long long b) {
    asm("fma.rn.f32x2 %0, %1, %2, %0;" : "+l"(acc) : "l"(a), "l"(b));
}
__device__ __forceinline__ void upk2(float& lo, float& hi, unsigned long long v) {
    asm("mov.b64 {%0, %1}, %2;" : "=f"(lo), "=f"(hi) : "l"(v));
}

// ---------------- spk matvec + bias fold ----------------
__global__ void spk_kernel(const float* __restrict__ w_spk, const float* __restrict__ spk,
                           const float* __restrict__ b_content, const float* __restrict__ b_spk,
                           const float* __restrict__ b_f0, const float* __restrict__ b_energy) {
    int b = blockIdx.x, o = threadIdx.x;
    __shared__ float sv[CSPK];
    if (o < CSPK) sv[o] = spk[b*CSPK + o];
    __syncthreads();
    float acc = 0.f;
    const float* wr = w_spk + (size_t)o*CSPK;
    #pragma unroll 4
    for (int c = 0; c < CSPK; c++) acc += wr[c]*sv[c];
    d_spkadd[b*CINT + o] = acc + b_content[o] + b_spk[o] + b_f0[o] + b_energy[o];
}

// ---------------- trunk GEMM (FFMA fp32; exact) ----------------
__global__ void __launch_bounds__(256) gemm_trunk(
    const float* __restrict__ W, const float* __restrict__ content,
    const float* __restrict__ f0, const float* __restrict__ energy,
    const float* __restrict__ wf0, const float* __restrict__ wen) {
    __shared__ float As[8][128];
    __shared__ float Bs[8][128];
    const int tid = threadIdx.x, b = blockIdx.z;
    const int m0 = blockIdx.x*128, t0 = blockIdx.y*128;
    const int tx = tid & 15, ty = tid >> 4;
    const int am = tid >> 1, ak = (tid & 1)*4;
    const int bk = tid >> 5, bn = (tid & 31)*4;
    float acc[8][8];
    #pragma unroll
    for (int i = 0; i < 8; i++)
        #pragma unroll
        for (int j = 0; j < 8; j++) acc[i][j] = 0.f;
    for (int k0 = 0; k0 < CCONT; k0 += 8) {
        float4 av = *(const float4*)(W + (size_t)(m0+am)*CCONT + k0 + ak);
        As[ak+0][am]=av.x; As[ak+1][am]=av.y; As[ak+2][am]=av.z; As[ak+3][am]=av.w;
        float4 bv = *(const float4*)(content + ((size_t)b*CCONT + k0 + bk)*TLEN + t0 + bn);
        *(float4*)&Bs[bk][bn] = bv;
        __syncthreads();
        #pragma unroll
        for (int kk = 0; kk < 8; kk++) {
            float a[8], bb[8];
            #pragma unroll
            for (int i = 0; i < 8; i++) a[i] = As[kk][ty*8+i];
            #pragma unroll
            for (int j = 0; j < 8; j++) bb[j] = Bs[kk][tx*8+j];
            #pragma unroll
            for (int i = 0; i < 8; i++)
                #pragma unroll
                for (int j = 0; j < 8; j++) acc[i][j] += a[i]*bb[j];
        }
        __syncthreads();
    }
    float lf[8], en[8];
    #pragma unroll
    for (int j = 0; j < 8; j++) {
        int t = t0 + tx*8 + j;
        float f = f0[b*TLEN + t];
        lf[j] = logf(fmaxf(f, 0.f) + 1e-6f);
        en[j] = energy[b*TLEN + t];
    }
    #pragma unroll
    for (int i = 0; i < 8; i++) {
        int m = m0 + ty*8 + i;
        float base = d_spkadd[b*CINT + m];
        float wf = wf0[m], we = wen[m];
        float* orow = d_x + ((size_t)b*CINT + m)*TLEN + t0 + tx*8;
        #pragma unroll
        for (int j = 0; j < 8; j++)
            orow[j] = acc[i][j] + base + wf*lf[j] + we*en[j];
    }
}

// ---------------- depthwise conv k=7 zero-pad ----------------
__global__ void dwconv_kernel(const float* __restrict__ w, const float* __restrict__ bias) {
    int t = blockIdx.x*256 + threadIdx.x;
    int c = blockIdx.y, b = blockIdx.z;
    const float* xr = d_x + ((size_t)b*CINT + c)*TLEN;
    float wv[7];
    #pragma unroll
    for (int k = 0; k < 7; k++) wv[k] = w[c*7 + k];
    float acc = bias[c];
    #pragma unroll
    for (int k = 0; k < 7; k++) {
        int tt = t + k - 3;
        if (tt >= 0 && tt < TLEN) acc += xr[tt]*wv[k];
    }
    d_h[((size_t)b*CINT + c)*TLEN + t] = acc;
}

// ---------------- channel-LN statistics ----------------
__global__ void stats_kernel(int which) {    // 0 -> d_h, 1 -> d_x
    const float* base = which ? d_x : d_h;
    int b = blockIdx.y;
    int t0 = blockIdx.x * 8;
    int tid = threadIdx.x;
    __shared__ float ssum[8][256];
    __shared__ float ssq[8][256];
    float s[8], q[8];
    #pragma unroll
    for (int j = 0; j < 8; j++) { s[j] = 0.f; q[j] = 0.f; }
    for (int c = tid; c < CINT; c += 256) {
        const float* p = base + ((size_t)b*CINT + c)*TLEN + t0;
        float4 v0 = *(const float4*)p;
        float4 v1 = *(const float4*)(p + 4);
        float v[8] = {v0.x,v0.y,v0.z,v0.w,v1.x,v1.y,v1.z,v1.w};
        #pragma unroll
        for (int j = 0; j < 8; j++) { s[j] += v[j]; q[j] += v[j]*v[j]; }
    }
    #pragma unroll
    for (int j = 0; j < 8; j++) { ssum[j][tid] = s[j]; ssq[j][tid] = q[j]; }
    __syncthreads();
    for (int step = 128; step > 0; step >>= 1) {
        if (tid < step) {
            #pragma unroll
            for (int j = 0; j < 8; j++) {
                ssum[j][tid] += ssum[j][tid+step];
                ssq[j][tid]  += ssq[j][tid+step];
            }
        }
        __syncthreads();
    }
    if (tid < 8) {
        float m = ssum[tid][0] * (1.f/CINT);
        float v = ssq[tid][0] * (1.f/CINT) - m*m;
        d_mu[b*TLEN + t0 + tid] = m;
        d_rs[b*TLEN + t0 + tid] = rsqrtf(v + 1e-6f);
    }
}

// ---------------- materialize final LN(x) into d_h ----------------
__global__ void lnorm_kernel(const float* __restrict__ g, const float* __restrict__ bv) {
    int t = blockIdx.x*256 + threadIdx.x;
    int c = blockIdx.y, b = blockIdx.z;
    float x = d_x[((size_t)b*CINT + c)*TLEN + t];
    d_h[((size_t)b*CINT + c)*TLEN + t] =
        (x - d_mu[b*TLEN + t]) * d_rs[b*TLEN + t] * g[c] + bv[c];
}

// ==================================================================
// fp16 m16n8k16 TC GEMMs (f32 accum): 128x128 block, BK=16,
// 8 warps (2x4) x 64x32 warp tile, double-buffered, one sync/iter.
// smem: packed half2 along K: As2[k2][m] = (A[m][2k2], A[m][2k2+1])
// ==================================================================
#define GEMM_DECLS \
    const int tid = threadIdx.x; \
    const int bb = blockIdx.z; \
    const int m0 = blockIdx.x * 128; \
    const int t0 = blockIdx.y * 128; \
    const int warp = tid >> 5, lane = tid & 31; \
    const int wm = (warp >> 2) * 64, wn = (warp & 3) * 32; \
    const int g = lane >> 2, tg = lane & 3; \
    const int am = tid >> 1, ak8 = (tid & 1) * 8, k2b = (tid & 1) * 4; \
    const int bkr2 = tid >> 5, bn = (tid & 31) * 4; \
    float acc[4][4][4]; \
    _Pragma("unroll") \
    for (int i=0;i<4;i++) \
        _Pragma("unroll") \
        for (int j=0;j<4;j++) \
            _Pragma("unroll") \
            for (int k=0;k<4;k++) acc[i][j][k]=0.f;

#define GEMM_COMPUTE(B_) { \
    uint32_t afr[4][4], bfr[4][2]; \
    _Pragma("unroll") \
    for (int mf=0; mf<4; mf++) { \
        int m = wm + mf*16 + g; \
        afr[mf][0] = As[B_][tg][m]; \
        afr[mf][1] = As[B_][tg][m+8]; \
        afr[mf][2] = As[B_][tg+4][m]; \
        afr[mf][3] = As[B_][tg+4][m+8]; \
    } \
    _Pragma("unroll") \
    for (int nf=0; nf<4; nf++) { \
        int n = wn + nf*8 + g; \
        bfr[nf][0] = Bs[B_][tg][n]; \
        bfr[nf][1] = Bs[B_][tg+4][n]; \
    } \
    _Pragma("unroll") \
    for (int mf=0;mf<4;mf++) \
        _Pragma("unroll") \
        for (int nf=0;nf<4;nf++) \
            mma_f16(acc[mf][nf], afr[mf], bfr[nf]); }

#define STORE_A(B_) { \
    As[B_][k2b+0][am] = pkh2(ra0.x, ra0.y); \
    As[B_][k2b+1][am] = pkh2(ra0.z, ra0.w); \
    As[B_][k2b+2][am] = pkh2(ra1.x, ra1.y); \
    As[B_][k2b+3][am] = pkh2(ra1.z, ra1.w); }

// ---------- pw1: d_g = gelu(W @ LN(d_h) + bias) ----------
__global__ void __launch_bounds__(256) gemm_pw1_tc(
    const float* __restrict__ W, const float* __restrict__ bias,
    const float* __restrict__ lng, const float* __restrict__ lnb) {
    __shared__ uint32_t As[2][8][136];
    __shared__ uint32_t Bs[2][8][136];
    GEMM_DECLS
    float4 muA = *(const float4*)(d_mu + bb*TLEN + t0 + bn);
    float4 rsA = *(const float4*)(d_rs + bb*TLEN + t0 + bn);
    float4 ra0, ra1, rb0, rb1;
    float g0, b0c, g1, b1c;

#define PW1_LOAD(K0) { \
    const float* ap = W + (size_t)(m0+am)*CINT + (K0) + ak8; \
    ra0 = *(const float4*)ap; ra1 = *(const float4*)(ap+4); \
    int c = (K0) + 2*bkr2; \
    const float* hp = d_h + ((size_t)bb*CINT + c)*TLEN + t0 + bn; \
    rb0 = *(const float4*)hp; rb1 = *(const float4*)(hp + TLEN); \
    g0 = lng[c]; b0c = lnb[c]; g1 = lng[c+1]; b1c = lnb[c+1]; }

#define PW1_STORE(B_) { \
    STORE_A(B_) \
    float l0 = (rb0.x-muA.x)*rsA.x*g0 + b0c, h0 = (rb1.x-muA.x)*rsA.x*g1 + b1c; \
    float l1 = (rb0.y-muA.y)*rsA.y*g0 + b0c, h1 = (rb1.y-muA.y)*rsA.y*g1 + b1c; \
    float l2 = (rb0.z-muA.z)*rsA.z*g0 + b0c, h2 = (rb1.z-muA.z)*rsA.z*g1 + b1c; \
    float l3 = (rb0.w-muA.w)*rsA.w*g0 + b0c, h3 = (rb1.w-muA.w)*rsA.w*g1 + b1c; \
    *(uint4*)&Bs[B_][bkr2][bn] = make_uint4(pkh2(l0,h0), pkh2(l1,h1), pkh2(l2,h2), pkh2(l3,h3)); }

    PW1_LOAD(0)
    PW1_STORE(0)
    __syncthreads();
    int buf = 0;
    #pragma unroll 1
    for (int k0 = 16; k0 < CINT; k0 += 16) {
        PW1_LOAD(k0)
        GEMM_COMPUTE(buf)
        PW1_STORE(buf^1)
        __syncthreads();
        buf ^= 1;
    }
    GEMM_COMPUTE(buf)

    #pragma unroll
    for (int mf=0;mf<4;mf++) {
        int m = m0 + wm + mf*16 + g;
        float bi0 = bias[m], bi1 = bias[m+8];
        #pragma unroll
        for (int nf=0;nf<4;nf++) {
            int t = t0 + wn + nf*8 + 2*tg;
            float* p0 = d_g + ((size_t)bb*DMLP + m)*TLEN + t;
            float* p1 = d_g + ((size_t)bb*DMLP + m+8)*TLEN + t;
            float2 o0, o1;
            o0.x = gelu_exact(acc[mf][nf][0] + bi0);
            o0.y = gelu_exact(acc[mf][nf][1] + bi0);
            o1.x = gelu_exact(acc[mf][nf][2] + bi1);
            o1.y = gelu_exact(acc[mf][nf][3] + bi1);
            *(float2*)p0 = o0;
            *(float2*)p1 = o1;
        }
    }
}

// ---------- pw2: d_x += W @ d_g + bias ----------
__global__ void __launch_bounds__(256) gemm_pw2_tc(
    const float* __restrict__ W, const float* __restrict__ bias) {
    __shared__ uint32_t As[2][8][136];
    __shared__ uint32_t Bs[2][8][136];
    GEMM_DECLS
    float4 ra0, ra1, rb0, rb1;

#define PW2_LOAD(K0) { \
    const float* ap = W + (size_t)(m0+am)*DMLP + (K0) + ak8; \
    ra0 = *(const float4*)ap; ra1 = *(const float4*)(ap+4); \
    const float* gp = d_g + ((size_t)bb*DMLP + (K0) + 2*bkr2)*TLEN + t0 + bn; \
    rb0 = *(const float4*)gp; rb1 = *(const float4*)(gp + TLEN); }

#define PW2_STORE(B_) { \
    STORE_A(B_) \
    *(uint4*)&Bs[B_][bkr2][bn] = make_uint4(pkh2(rb0.x,rb1.x), pkh2(rb0.y,rb1.y), \
                                            pkh2(rb0.z,rb1.z), pkh2(rb0.w,rb1.w)); }

    PW2_LOAD(0)
    PW2_STORE(0)
    __syncthreads();
    int buf = 0;
    #pragma unroll 1
    for (int k0 = 16; k0 < DMLP; k0 += 16) {
        PW2_LOAD(k0)
        GEMM_COMPUTE(buf)
        PW2_STORE(buf^1)
        __syncthreads();
        buf ^= 1;
    }
    GEMM_COMPUTE(buf)

    #pragma unroll
    for (int mf=0;mf<4;mf++) {
        int m = m0 + wm + mf*16 + g;
        float bi0 = bias[m], bi1 = bias[m+8];
        #pragma unroll
        for (int nf=0;nf<4;nf++) {
            int t = t0 + wn + nf*8 + 2*tg;
            float* p0 = d_x + ((size_t)bb*CINT + m)*TLEN + t;
            float* p1 = d_x + ((size_t)bb*CINT + m+8)*TLEN + t;
            float2 r0 = *(float2*)p0;
            float2 r1 = *(float2*)p1;
            r0.x += acc[mf][nf][0] + bi0;
            r0.y += acc[mf][nf][1] + bi0;
            r1.x += acc[mf][nf][2] + bi1;
            r1.y += acc[mf][nf][3] + bi1;
            *(float2*)p0 = r0;
            *(float2*)p1 = r1;
        }
    }
}

// ---------- outconv: filt = Wout (*) LN(x) (im2col K=3584) ----------
__global__ void __launch_bounds__(256) gemm_out_tc(
    const float* __restrict__ W, const float* __restrict__ bias) {
    __shared__ uint32_t As[2][8][136];
    __shared__ uint32_t Bs[2][8][136];
    GEMM_DECLS
    float4 ra0, ra1;
    float rx0[4], rx1[4];

#define OUT_LOAD(K0) { \
    const float* ap = W + (size_t)(m0+am)*KOUT + (K0) + ak8; \
    ra0 = *(const float4*)ap; ra1 = *(const float4*)(ap+4); \
    int r = (K0) + 2*bkr2; \
    { int c = r / 7, k7 = r - c*7; \
      const float* xr = d_h + ((size_t)bb*CINT + c)*TLEN; \
      _Pragma("unroll") \
      for (int j = 0; j < 4; j++) { \
          int t = t0 + bn + j + k7 - 3; \
          t = t < 0 ? 0 : (t > TLEN-1 ? TLEN-1 : t); \
          rx0[j] = xr[t]; } } \
    { int c = (r+1) / 7, k7 = (r+1) - c*7; \
      const float* xr = d_h + ((size_t)bb*CINT + c)*TLEN; \
      _Pragma("unroll") \
      for (int j = 0; j < 4; j++) { \
          int t = t0 + bn + j + k7 - 3; \
          t = t < 0 ? 0 : (t > TLEN-1 ? TLEN-1 : t); \
          rx1[j] = xr[t]; } } }

#define OUT_STORE(B_) { \
    STORE_A(B_) \
    *(uint4*)&Bs[B_][bkr2][bn] = make_uint4(pkh2(rx0[0],rx1[0]), pkh2(rx0[1],rx1[1]), \
                                            pkh2(rx0[2],rx1[2]), pkh2(rx0[3],rx1[3])); }

    OUT_LOAD(0)
    OUT_STORE(0)
    __syncthreads();
    int buf = 0;
    #pragma unroll 1
    for (int k0 = 16; k0 < KOUT; k0 += 16) {
        OUT_LOAD(k0)
        GEMM_COMPUTE(buf)
        OUT_STORE(buf^1)
        __syncthreads();
        buf ^= 1;
    }
    GEMM_COMPUTE(buf)

    #pragma unroll
    for (int mf=0;mf<4;mf++) {
        int w = m0 + wm + mf*16 + g;
        float bw0 = bias[w], bw1 = bias[w+8];
        #pragma unroll
        for (int nf=0;nf<4;nf++) {
            int t = t0 + wn + nf*8 + 2*tg;
            float* base0 = d_filt + ((size_t)(bb*TLEN + t))*NWIN;
            float* base1 = d_filt + ((size_t)(bb*TLEN + t+1))*NWIN;
            base0[w]   = acc[mf][nf][0] + bw0;
            base1[w]   = acc[mf][nf][1] + bw0;
            base0[w+8] = acc[mf][nf][2] + bw1;
            base1[w+8] = acc[mf][nf][3] + bw1;
        }
    }
}

// ---------------- zero output ----------------
__global__ void zero_kernel(float* __restrict__ out) {
    size_t i = ((size_t)blockIdx.x*256 + threadIdx.x)*4;
    *(float4*)(out + i) = make_float4(0.f,0.f,0.f,0.f);
}

// ---------------- per-frame FIR + overlap-add, pre-packed f32x2 ----------------
__global__ void __launch_bounds__(256) fir4_kernel(const float* __restrict__ src,
                                                   float* __restrict__ out) {
    const int f = blockIdx.x, b = blockIdx.y;
    __shared__ __align__(16) float2 s_fk[1024];
    __shared__ __align__(16) float2 s_even[1544];
    __shared__ __align__(16) float2 s_odd[1544];
    const int tid = threadIdx.x;
    const float* sb = src + (size_t)b*LTOT + (size_t)f*FRAME;

    for (int j = tid; j < 1536; j += 256) {
        int i0 = 2*j - 1024;
        float a = (i0   >= 0 && i0   < FRAME) ? sb[i0]   : 0.f;
        float m = (i0+1 >= 0 && i0+1 < FRAME) ? sb[i0+1] : 0.f;
        float c = (i0+2 >= 0 && i0+2 < FRAME) ? sb[i0+2] : 0.f;
        s_even[j] = make_float2(a, m);
        s_odd[j]  = make_float2(m, c);
    }
    for (int k = tid; k < 1024; k += 256) {
        float fv = d_filt[((size_t)(b*TLEN + f))*NWIN + k];
        s_fk[k] = make_float2(fv, fv);
    }
    __syncthreads();

    if (tid >= 248) return;
    const int j0 = tid*8;
    unsigned long long accp[4] = {0ull, 0ull, 0ull, 0ull};
    const ulonglong2* FK = (const ulonglong2*)s_fk;
    const ulonglong2* EV = (const ulonglong2*)s_even;
    const ulonglong2* OD = (const ulonglong2*)s_odd;

    #pragma unroll 1
    for (int kc = 0; kc < 1024; kc += 8) {
        int fk2 = kc >> 1;              // ull2 index into FK
        ulonglong2 f0 = FK[fk2+0], f1 = FK[fk2+1], f2 = FK[fk2+2], f3 = FK[fk2+3];
        int pe = 2*tid + (kc >> 2);     // ull2 index into EV/OD
        ulonglong2 e0 = EV[pe+0], e1 = EV[pe+1], e2 = EV[pe+2], e3 = EV[pe+3];
        ulonglong2 o0 = OD[pe+0], o1 = OD[pe+1], o2 = OD[pe+2], o3 = OD[pe+3];
        unsigned long long fkp[8] = {f0.x,f0.y,f1.x,f1.y,f2.x,f2.y,f3.x,f3.y};
        unsigned long long Ap[8]  = {e0.x,e0.y,e1.x,e1.y,e2.x,e2.y,e3.x,e3.y};
        unsigned long long Bp[8]  = {o0.x,o0.y,o1.x,o1.y,o2.x,o2.y,o3.x,o3.y};
        #pragma unroll
        for (int q = 0; q < 8; q += 2) {
            #pragma unroll
            for (int r2 = 0; r2 < 4; r2++) fma2(accp[r2], fkp[q],   Ap[q/2 + r2]);
            #pragma unroll
            for (int r2 = 0; r2 < 4; r2++) fma2(accp[r2], fkp[q+1], Bp[q/2 + r2]);
        }
    }

    float accf[8];
    #pragma unroll
    for (int r2 = 0; r2 < 4; r2++) upk2(accf[2*r2], accf[2*r2+1], accp[r2]);
    const int u0 = f*FRAME + j0;
    #pragma unroll
    for (int r = 0; r < 8; r++) {
        int j = j0 + r, u = u0 + r;
        if (j >= 1 && u < LTOT)
            atomicAdd(out + (size_t)b*LTOT + u, accf[r]);
    }
}

// ---------------- host launcher ----------------
extern "C" void kernel_launch(void* const* d_in, const int* in_sizes, int n_in,
                              void* d_out, int out_size) {
    const float* content  = (const float*)d_in[0];
    const float* f0       = (const float*)d_in[1];
    const float* energy   = (const float*)d_in[2];
    const float* spk      = (const float*)d_in[3];
    const float* source   = (const float*)d_in[4];
    const float* w_content= (const float*)d_in[5];
    const float* b_content= (const float*)d_in[6];
    const float* w_spk    = (const float*)d_in[7];
    const float* b_spk    = (const float*)d_in[8];
    const float* w_f0     = (const float*)d_in[9];
    const float* b_f0     = (const float*)d_in[10];
    const float* w_energy = (const float*)d_in[11];
    const float* b_energy = (const float*)d_in[12];
    const float* dw_w     = (const float*)d_in[13];
    const float* dw_b     = (const float*)d_in[14];
    const float* ln_g     = (const float*)d_in[15];
    const float* ln_b     = (const float*)d_in[16];
    const float* pw1_w    = (const float*)d_in[17];
    const float* pw1_b    = (const float*)d_in[18];
    const float* pw2_w    = (const float*)d_in[19];
    const float* pw2_b    = (const float*)d_in[20];
    const float* out_ln_g = (const float*)d_in[21];
    const float* out_ln_b = (const float*)d_in[22];
    const float* w_out    = (const float*)d_in[23];
    const float* b_out    = (const float*)d_in[24];
    float* out = (float*)d_out;

    zero_kernel<<<BATCH*LTOT/1024, 256>>>(out);
    spk_kernel<<<BATCH, 512>>>(w_spk, spk, b_content, b_spk, b_f0, b_energy);
    gemm_trunk<<<dim3(CINT/128, TLEN/128, BATCH), 256>>>(w_content, content, f0, energy,
                                                         w_f0, w_energy);
    for (int l = 0; l < 6; l++) {
        dwconv_kernel<<<dim3(TLEN/256, CINT, BATCH), 256>>>(dw_w + (size_t)l*CINT*7,
                                                            dw_b + (size_t)l*CINT);
        stats_kernel<<<dim3(TLEN/8, BATCH), 256>>>(0);
        gemm_pw1_tc<<<dim3(DMLP/128, TLEN/128, BATCH), 256>>>(pw1_w + (size_t)l*DMLP*CINT,
                                                              pw1_b + (size_t)l*DMLP,
                                                              ln_g + (size_t)l*CINT,
                                                              ln_b + (size_t)l*CINT);
        gemm_pw2_tc<<<dim3(CINT/128, TLEN/128, BATCH), 256>>>(pw2_w + (size_t)l*CINT*DMLP,
                                                              pw2_b + (size_t)l*CINT);
    }
    stats_kernel<<<dim3(TLEN/8, BATCH), 256>>>(1);
    lnorm_kernel<<<dim3(TLEN/256, CINT, BATCH), 256>>>(out_ln_g, out_ln_b);
    gemm_out_tc<<<dim3(NWIN/128, TLEN/128, BATCH), 256>>>(w_out, b_out);
    fir4_kernel<<<dim3(TLEN, BATCH), 256>>>(source, out);
}

// round 9
// speedup vs baseline: 1.1053x; 1.1053x over previous
#include <cuda_runtime.h>
#include <cuda_fp16.h>
#include <stdint.h>
#include <math.h>

#define BATCH 8
#define TLEN  512
#define CINT  512
#define CCONT 192
#define CSPK  256
#define DMLP  1536
#define NWIN  1024
#define FRAME 960
#define LTOT  (TLEN*FRAME)
#define KOUT  3584

// ---------------- scratch (device globals; t-major activations [B][T][C]) ----------------
__device__ __align__(256) float  d_x[BATCH*TLEN*CINT];     // residual stream fp32
__device__ __align__(256) __half d_h2[BATCH*TLEN*CINT];    // LN'd dwconv out (GEMM A)
__device__ __align__(256) __half d_g2[BATCH*TLEN*DMLP];    // gelu out (GEMM A for pw2)
__device__ __align__(256) __half d_w1h[6*DMLP*CINT];
__device__ __align__(256) __half d_w2h[6*CINT*DMLP];
__device__ __align__(256) __half d_wOh[NWIN*KOUT];         // permuted [w][kappa*512+c]
__device__ __align__(256) float  d_filt[BATCH*TLEN*NWIN];
__device__ float d_spkadd[BATCH*CINT];

// ---------------- helpers ----------------
__device__ __forceinline__ uint32_t pkh2(float lo, float hi) {
    uint32_t r;
    asm("cvt.rn.f16x2.f32 %0, %1, %2;" : "=r"(r) : "f"(hi), "f"(lo));
    return r;
}
__device__ __forceinline__ void mma_f16(float c[4], const uint32_t a[4], const uint32_t b[2]) {
    asm volatile("mma.sync.aligned.m16n8k16.row.col.f32.f16.f16.f32 "
                 "{%0,%1,%2,%3},{%4,%5,%6,%7},{%8,%9},{%0,%1,%2,%3};"
                 : "+f"(c[0]), "+f"(c[1]), "+f"(c[2]), "+f"(c[3])
                 : "r"(a[0]), "r"(a[1]), "r"(a[2]), "r"(a[3]), "r"(b[0]), "r"(b[1]));
}
__device__ __forceinline__ float gelu_exact(float v) {
    return 0.5f*v*(1.f + erff(v*0.70710678118654752f));
}
__device__ __forceinline__ void fma2(unsigned long long& acc, unsigned long long a,
                                     unsigned long long b) {
    asm("fma.rn.f32x2 %0, %1, %2, %0;" : "+l"(acc) : "l"(a), "l"(b));
}
__device__ __forceinline__ void upk2(float& lo, float& hi, unsigned long long v) {
    asm("mov.b64 {%0, %1}, %2;" : "=f"(lo), "=f"(hi) : "l"(v));
}

// ---------------- prep: weight conversions ----------------
__global__ void cvth_kernel(const float* __restrict__ s, __half* __restrict__ d) {
    size_t i = ((size_t)blockIdx.x*256 + threadIdx.x)*4;
    float4 v = *(const float4*)(s + i);
    uint2 o;
    o.x = pkh2(v.x, v.y);
    o.y = pkh2(v.z, v.w);
    *(uint2*)(d + i) = o;
}
__global__ void permw_kernel(const float* __restrict__ w_out) {
    int idx = blockIdx.x*256 + threadIdx.x;
    int w = idx / KOUT;
    int r = idx - w*KOUT;
    int kap = r >> 9, c = r & 511;
    d_wOh[idx] = __float2half(w_out[((size_t)w*CINT + c)*7 + kap]);
}

// ---------------- spk matvec + bias fold ----------------
__global__ void spk_kernel(const float* __restrict__ w_spk, const float* __restrict__ spk,
                           const float* __restrict__ b_content, const float* __restrict__ b_spk,
                           const float* __restrict__ b_f0, const float* __restrict__ b_energy) {
    int b = blockIdx.x, o = threadIdx.x;
    __shared__ float sv[CSPK];
    if (o < CSPK) sv[o] = spk[b*CSPK + o];
    __syncthreads();
    float acc = 0.f;
    const float* wr = w_spk + (size_t)o*CSPK;
    #pragma unroll 4
    for (int c = 0; c < CSPK; c++) acc += wr[c]*sv[c];
    d_spkadd[b*CINT + o] = acc + b_content[o] + b_spk[o] + b_f0[o] + b_energy[o];
}

// ---------------- trunk GEMM (FFMA fp32), writes d_x t-major ----------------
__global__ void __launch_bounds__(256) gemm_trunk(
    const float* __restrict__ W, const float* __restrict__ content,
    const float* __restrict__ f0, const float* __restrict__ energy,
    const float* __restrict__ wf0, const float* __restrict__ wen) {
    __shared__ float As[8][128];
    __shared__ float Bs[8][128];
    const int tid = threadIdx.x, b = blockIdx.z;
    const int m0 = blockIdx.x*128, t0 = blockIdx.y*128;
    const int tx = tid & 15, ty = tid >> 4;
    const int am = tid >> 1, ak = (tid & 1)*4;
    const int bk = tid >> 5, bn = (tid & 31)*4;
    float acc[8][8];
    #pragma unroll
    for (int i = 0; i < 8; i++)
        #pragma unroll
        for (int j = 0; j < 8; j++) acc[i][j] = 0.f;
    for (int k0 = 0; k0 < CCONT; k0 += 8) {
        float4 av = *(const float4*)(W + (size_t)(m0+am)*CCONT + k0 + ak);
        As[ak+0][am]=av.x; As[ak+1][am]=av.y; As[ak+2][am]=av.z; As[ak+3][am]=av.w;
        float4 bv = *(const float4*)(content + ((size_t)b*CCONT + k0 + bk)*TLEN + t0 + bn);
        *(float4*)&Bs[bk][bn] = bv;
        __syncthreads();
        #pragma unroll
        for (int kk = 0; kk < 8; kk++) {
            float a[8], bb[8];
            #pragma unroll
            for (int i = 0; i < 8; i++) a[i] = As[kk][ty*8+i];
            #pragma unroll
            for (int j = 0; j < 8; j++) bb[j] = Bs[kk][tx*8+j];
            #pragma unroll
            for (int i = 0; i < 8; i++)
                #pragma unroll
                for (int j = 0; j < 8; j++) acc[i][j] += a[i]*bb[j];
        }
        __syncthreads();
    }
    float lf[8], en[8];
    #pragma unroll
    for (int j = 0; j < 8; j++) {
        int t = t0 + tx*8 + j;
        float f = f0[b*TLEN + t];
        lf[j] = logf(fmaxf(f, 0.f) + 1e-6f);
        en[j] = energy[b*TLEN + t];
    }
    #pragma unroll
    for (int i = 0; i < 8; i++) {
        int m = m0 + ty*8 + i;
        float base = d_spkadd[b*CINT + m];
        float wf = wf0[m], we = wen[m];
        #pragma unroll
        for (int j = 0; j < 8; j++) {
            int t = t0 + tx*8 + j;
            d_x[((size_t)b*TLEN + t)*CINT + m] = acc[i][j] + base + wf*lf[j] + we*en[j];
        }
    }
}

// ---------------- fused dwconv(k=7,zero-pad) + LN stats + normalize -> half2 ----------------
// DW=true: h = dwconv(d_x); DW=false: h = d_x.  Output d_h2 (LN'd, half).
template<bool DW>
__global__ void __launch_bounds__(256) dwstats(const float* __restrict__ dww,
                                               const float* __restrict__ dwb,
                                               const float* __restrict__ lng,
                                               const float* __restrict__ lnb) {
    const int b = blockIdx.y;
    const int t0 = blockIdx.x * 8;
    const int tid = threadIdx.x;
    const int c0 = 2*tid;
    __shared__ float ssum[8][256];
    __shared__ float ssq[8][256];

    float h[8][2];
    if (DW) {
        float2 wv[7];
        #pragma unroll
        for (int k = 0; k < 7; k++) {
            wv[k].x = dww[c0*7 + k];
            wv[k].y = dww[(c0+1)*7 + k];
        }
        float bx = dwb[c0], by = dwb[c0+1];
        float2 xv[14];
        #pragma unroll
        for (int j = 0; j < 14; j++) {
            int row = t0 + j - 3;
            if (row >= 0 && row < TLEN)
                xv[j] = *(const float2*)(d_x + ((size_t)b*TLEN + row)*CINT + c0);
            else
                xv[j] = make_float2(0.f, 0.f);
        }
        #pragma unroll
        for (int j = 0; j < 8; j++) {
            float a = bx, c = by;
            #pragma unroll
            for (int k = 0; k < 7; k++) {
                a += wv[k].x * xv[j+k].x;
                c += wv[k].y * xv[j+k].y;
            }
            h[j][0] = a; h[j][1] = c;
        }
    } else {
        #pragma unroll
        for (int j = 0; j < 8; j++) {
            float2 v = *(const float2*)(d_x + ((size_t)b*TLEN + t0 + j)*CINT + c0);
            h[j][0] = v.x; h[j][1] = v.y;
        }
    }

    #pragma unroll
    for (int j = 0; j < 8; j++) {
        ssum[j][tid] = h[j][0] + h[j][1];
        ssq[j][tid]  = h[j][0]*h[j][0] + h[j][1]*h[j][1];
    }
    __syncthreads();
    for (int step = 128; step > 0; step >>= 1) {
        if (tid < step) {
            #pragma unroll
            for (int j = 0; j < 8; j++) {
                ssum[j][tid] += ssum[j][tid+step];
                ssq[j][tid]  += ssq[j][tid+step];
            }
        }
        __syncthreads();
    }
    float g0 = lng[c0], g1 = lng[c0+1];
    float b0 = lnb[c0], b1 = lnb[c0+1];
    #pragma unroll
    for (int j = 0; j < 8; j++) {
        float mu = ssum[j][0] * (1.f/CINT);
        float rs = rsqrtf(ssq[j][0] * (1.f/CINT) - mu*mu + 1e-6f);
        float lo = (h[j][0]-mu)*rs*g0 + b0;
        float hi = (h[j][1]-mu)*rs*g1 + b1;
        *(uint32_t*)&d_h2[((size_t)b*TLEN + t0 + j)*CINT + c0] = pkh2(lo, hi);
    }
}

// ==================================================================
// fp16 m16n8k16 GEMM, zero-conversion hot loop.
// A = activation [t][k] (half, t-major), B = weight [out][k] (half).
// C[t][out]. 128x128 tile, BK=16, 8 warps (2x4), double-buffered.
// MODE 0: pw1 (K=CINT,  epi gelu+bias -> d_g2 half)
// MODE 1: pw2 (K=DMLP,  epi +bias+residual -> d_x fp32)
// MODE 2: out (K=KOUT,  A=im2col(d_h2) clamp, epi +bias -> d_filt fp32)
// ==================================================================
#define GEMM_COMPUTE(B_) { \
    uint32_t afr[4][4], bfr[4][2]; \
    _Pragma("unroll") \
    for (int mf=0; mf<4; mf++) { \
        int m = wm + mf*16 + g; \
        afr[mf][0] = As[B_][tg][m]; \
        afr[mf][1] = As[B_][tg][m+8]; \
        afr[mf][2] = As[B_][tg+4][m]; \
        afr[mf][3] = As[B_][tg+4][m+8]; \
    } \
    _Pragma("unroll") \
    for (int nf=0; nf<4; nf++) { \
        int n = wn + nf*8 + g; \
        bfr[nf][0] = Bs[B_][tg][n]; \
        bfr[nf][1] = Bs[B_][tg+4][n]; \
    } \
    _Pragma("unroll") \
    for (int mf=0;mf<4;mf++) \
        _Pragma("unroll") \
        for (int nf=0;nf<4;nf++) \
            mma_f16(acc[mf][nf], afr[mf], bfr[nf]); }

#define G_LOAD(K0) { \
    const __half* ap_; \
    if (MODE == 2) { \
        int kap = (K0) >> 9; \
        int te = t0 + am + kap - 3; \
        te = te < 0 ? 0 : (te > TLEN-1 ? TLEN-1 : te); \
        ap_ = Aact + ((size_t)bb*TLEN + te)*CINT + (((K0) & 511) + kh8); \
    } else { \
        ap_ = Aact + ((size_t)bb*TLEN + t0 + am)*ROWL + (K0) + kh8; \
    } \
    ra = *(const uint4*)ap_; \
    rb = *(const uint4*)(Wh + (size_t)(n0+am)*KTOT + (K0) + kh8); }

#define G_STORE(S) { \
    As[S][k2b+0][am]=ra.x; As[S][k2b+1][am]=ra.y; \
    As[S][k2b+2][am]=ra.z; As[S][k2b+3][am]=ra.w; \
    Bs[S][k2b+0][am]=rb.x; Bs[S][k2b+1][am]=rb.y; \
    Bs[S][k2b+2][am]=rb.z; Bs[S][k2b+3][am]=rb.w; }

template<int KTOT, int MODE>
__global__ void __launch_bounds__(256) gemm5(const __half* __restrict__ Aact,
                                             const __half* __restrict__ Wh,
                                             const float* __restrict__ bias) {
    __shared__ uint32_t As[2][8][136];
    __shared__ uint32_t Bs[2][8][136];
    const int tid = threadIdx.x;
    const int bb = blockIdx.z;
    const int t0 = blockIdx.x * 128;
    const int n0 = blockIdx.y * 128;
    const int warp = tid >> 5, lane = tid & 31;
    const int wm = (warp >> 2) * 64, wn = (warp & 3) * 32;
    const int g = lane >> 2, tg = lane & 3;
    const int am = tid >> 1;
    const int kh8 = (tid & 1) * 8;
    const int k2b = (tid & 1) * 4;
    constexpr int ROWL = (MODE == 1) ? DMLP : CINT;

    float acc[4][4][4];
    #pragma unroll
    for (int i=0;i<4;i++)
        #pragma unroll
        for (int j=0;j<4;j++)
            #pragma unroll
            for (int k=0;k<4;k++) acc[i][j][k]=0.f;

    uint4 ra, rb;
    G_LOAD(0)
    G_STORE(0)
    __syncthreads();
    int buf = 0;
    #pragma unroll 1
    for (int k0 = 16; k0 < KTOT; k0 += 16) {
        G_LOAD(k0)
        GEMM_COMPUTE(buf)
        G_STORE(buf^1)
        __syncthreads();
        buf ^= 1;
    }
    GEMM_COMPUTE(buf)

    #pragma unroll
    for (int mf=0;mf<4;mf++) {
        int t = t0 + wm + mf*16 + g;
        #pragma unroll
        for (int nf=0;nf<4;nf++) {
            int n = n0 + wn + nf*8 + 2*tg;
            float2 bi = *(const float2*)(bias + n);
            float v00 = acc[mf][nf][0] + bi.x;
            float v01 = acc[mf][nf][1] + bi.y;
            float v10 = acc[mf][nf][2] + bi.x;
            float v11 = acc[mf][nf][3] + bi.y;
            if (MODE == 0) {
                v00 = gelu_exact(v00); v01 = gelu_exact(v01);
                v10 = gelu_exact(v10); v11 = gelu_exact(v11);
                *(uint32_t*)&d_g2[((size_t)bb*TLEN + t  )*DMLP + n] = pkh2(v00, v01);
                *(uint32_t*)&d_g2[((size_t)bb*TLEN + t+8)*DMLP + n] = pkh2(v10, v11);
            } else if (MODE == 1) {
                float* p0 = d_x + ((size_t)bb*TLEN + t  )*CINT + n;
                float* p1 = d_x + ((size_t)bb*TLEN + t+8)*CINT + n;
                float2 r0 = *(float2*)p0;
                float2 r1 = *(float2*)p1;
                r0.x += v00; r0.y += v01;
                r1.x += v10; r1.y += v11;
                *(float2*)p0 = r0;
                *(float2*)p1 = r1;
            } else {
                *(float2*)(d_filt + ((size_t)bb*TLEN + t  )*NWIN + n) = make_float2(v00, v01);
                *(float2*)(d_filt + ((size_t)bb*TLEN + t+8)*NWIN + n) = make_float2(v10, v11);
            }
        }
    }
}

// ---------------- zero output ----------------
__global__ void zero_kernel(float* __restrict__ out) {
    size_t i = ((size_t)blockIdx.x*256 + threadIdx.x)*4;
    *(float4*)(out + i) = make_float4(0.f,0.f,0.f,0.f);
}

// ---------------- per-frame FIR + overlap-add, pre-packed f32x2 ----------------
__global__ void __launch_bounds__(256) fir4_kernel(const float* __restrict__ src,
                                                   float* __restrict__ out) {
    const int f = blockIdx.x, b = blockIdx.y;
    __shared__ __align__(16) float2 s_fk[1024];
    __shared__ __align__(16) float2 s_even[1544];
    __shared__ __align__(16) float2 s_odd[1544];
    const int tid = threadIdx.x;
    const float* sb = src + (size_t)b*LTOT + (size_t)f*FRAME;

    for (int j = tid; j < 1536; j += 256) {
        int i0 = 2*j - 1024;
        float a = (i0   >= 0 && i0   < FRAME) ? sb[i0]   : 0.f;
        float m = (i0+1 >= 0 && i0+1 < FRAME) ? sb[i0+1] : 0.f;
        float c = (i0+2 >= 0 && i0+2 < FRAME) ? sb[i0+2] : 0.f;
        s_even[j] = make_float2(a, m);
        s_odd[j]  = make_float2(m, c);
    }
    for (int k = tid; k < 1024; k += 256) {
        float fv = d_filt[((size_t)(b*TLEN + f))*NWIN + k];
        s_fk[k] = make_float2(fv, fv);
    }
    __syncthreads();

    if (tid >= 248) return;
    const int j0 = tid*8;
    unsigned long long accp[4] = {0ull, 0ull, 0ull, 0ull};
    const ulonglong2* FK = (const ulonglong2*)s_fk;
    const ulonglong2* EV = (const ulonglong2*)s_even;
    const ulonglong2* OD = (const ulonglong2*)s_odd;

    #pragma unroll 1
    for (int kc = 0; kc < 1024; kc += 8) {
        int fk2 = kc >> 1;
        ulonglong2 f0 = FK[fk2+0], f1 = FK[fk2+1], f2 = FK[fk2+2], f3 = FK[fk2+3];
        int pe = 2*tid + (kc >> 2);
        ulonglong2 e0 = EV[pe+0], e1 = EV[pe+1], e2 = EV[pe+2], e3 = EV[pe+3];
        ulonglong2 o0 = OD[pe+0], o1 = OD[pe+1], o2 = OD[pe+2], o3 = OD[pe+3];
        unsigned long long fkp[8] = {f0.x,f0.y,f1.x,f1.y,f2.x,f2.y,f3.x,f3.y};
        unsigned long long Ap[8]  = {e0.x,e0.y,e1.x,e1.y,e2.x,e2.y,e3.x,e3.y};
        unsigned long long Bp[8]  = {o0.x,o0.y,o1.x,o1.y,o2.x,o2.y,o3.x,o3.y};
        #pragma unroll
        for (int q = 0; q < 8; q += 2) {
            #pragma unroll
            for (int r2 = 0; r2 < 4; r2++) fma2(accp[r2], fkp[q],   Ap[q/2 + r2]);
            #pragma unroll
            for (int r2 = 0; r2 < 4; r2++) fma2(accp[r2], fkp[q+1], Bp[q/2 + r2]);
        }
    }

    float accf[8];
    #pragma unroll
    for (int r2 = 0; r2 < 4; r2++) upk2(accf[2*r2], accf[2*r2+1], accp[r2]);
    const int u0 = f*FRAME + j0;
    #pragma unroll
    for (int r = 0; r < 8; r++) {
        int j = j0 + r, u = u0 + r;
        if (j >= 1 && u < LTOT)
            atomicAdd(out + (size_t)b*LTOT + u, accf[r]);
    }
}

// ---------------- host launcher ----------------
extern "C" void kernel_launch(void* const* d_in, const int* in_sizes, int n_in,
                              void* d_out, int out_size) {
    const float* content  = (const float*)d_in[0];
    const float* f0       = (const float*)d_in[1];
    const float* energy   = (const float*)d_in[2];
    const float* spk      = (const float*)d_in[3];
    const float* source   = (const float*)d_in[4];
    const float* w_content= (const float*)d_in[5];
    const float* b_content= (const float*)d_in[6];
    const float* w_spk    = (const float*)d_in[7];
    const float* b_spk    = (const float*)d_in[8];
    const float* w_f0     = (const float*)d_in[9];
    const float* b_f0     = (const float*)d_in[10];
    const float* w_energy = (const float*)d_in[11];
    const float* b_energy = (const float*)d_in[12];
    const float* dw_w     = (const float*)d_in[13];
    const float* dw_b     = (const float*)d_in[14];
    const float* ln_g     = (const float*)d_in[15];
    const float* ln_b     = (const float*)d_in[16];
    const float* pw1_w    = (const float*)d_in[17];
    const float* pw1_b    = (const float*)d_in[18];
    const float* pw2_w    = (const float*)d_in[19];
    const float* pw2_b    = (const float*)d_in[20];
    const float* out_ln_g = (const float*)d_in[21];
    const float* out_ln_b = (const float*)d_in[22];
    const float* w_out    = (const float*)d_in[23];
    const float* b_out    = (const float*)d_in[24];
    float* out = (float*)d_out;

    __half *w1h, *w2h, *wOh, *h2g, *g2g;
    cudaGetSymbolAddress((void**)&w1h, d_w1h);
    cudaGetSymbolAddress((void**)&w2h, d_w2h);
    cudaGetSymbolAddress((void**)&wOh, d_wOh);
    cudaGetSymbolAddress((void**)&h2g, d_h2);
    cudaGetSymbolAddress((void**)&g2g, d_g2);

    zero_kernel<<<BATCH*LTOT/1024, 256>>>(out);
    cvth_kernel<<<6*DMLP*CINT/1024, 256>>>(pw1_w, w1h);
    cvth_kernel<<<6*CINT*DMLP/1024, 256>>>(pw2_w, w2h);
    permw_kernel<<<NWIN*KOUT/256, 256>>>(w_out);
    spk_kernel<<<BATCH, 512>>>(w_spk, spk, b_content, b_spk, b_f0, b_energy);
    gemm_trunk<<<dim3(CINT/128, TLEN/128, BATCH), 256>>>(w_content, content, f0, energy,
                                                         w_f0, w_energy);
    for (int l = 0; l < 6; l++) {
        dwstats<true><<<dim3(TLEN/8, BATCH), 256>>>(dw_w + (size_t)l*CINT*7,
                                                    dw_b + (size_t)l*CINT,
                                                    ln_g + (size_t)l*CINT,
                                                    ln_b + (size_t)l*CINT);
        gemm5<CINT,0><<<dim3(4, DMLP/128, BATCH), 256>>>(
            h2g, w1h + (size_t)l*DMLP*CINT, pw1_b + (size_t)l*DMLP);
        gemm5<DMLP,1><<<dim3(4, CINT/128, BATCH), 256>>>(
            g2g, w2h + (size_t)l*CINT*DMLP, pw2_b + (size_t)l*CINT);
    }
    dwstats<false><<<dim3(TLEN/8, BATCH), 256>>>(nullptr, nullptr, out_ln_g, out_ln_b);
    gemm5<KOUT,2><<<dim3(4, NWIN/128, BATCH), 256>>>(h2g, wOh, b_out);
    fir4_kernel<<<dim3(TLEN, BATCH), 256>>>(source, out);
}